// round 15
// baseline (speedup 1.0000x reference)
#include <cuda_runtime.h>
#include <cuda_fp16.h>
#include <math.h>
#include <stdint.h>

// Problem constants
#define NN    50000
#define NE    1600000
#define INDIM 512
#define HD1   256
#define HD2R  129     // real cols of layer 2
#define HD2P  136     // padded stride in halves (272B, 16B-aligned)

#define SCAN_B 512
#define NBLK   ((NN + SCAN_B - 1) / SCAN_B)   // 98

#define W0CHUNKS (INDIM * HD1 / 8)      // 16384
#define INITW_N  (HD1 * HD2P)           // 34816 (> W0CHUNKS)

// ---------------- static scratch (no allocations allowed) ----------------
// d_cnt invariant: zero at module load; k_scanfuse re-zeroes it after use.
// d_arr invariant: zero at load; releaser block re-zeroes before flag release.
__device__ __half d_W0h[INDIM * HD1];         // fp16 W0 [K=512][N=256]
__device__ __half d_W1h[HD1 * HD2P];          // fp16 W1, padded
__device__ __half d_HAh[(size_t)NN * HD1];    // fp16 XW0; reused as H1W1 (stride HD2P)
__device__ __half d_HB[(size_t)NN * HD1];     // fp16 softplus(agg1)
__device__ int    d_col[NE];
__device__ int    d_rp[NN + 1];
__device__ int    d_cur[NN];
__device__ int    d_cnt[NN];
__device__ float  d_dinv[NN];
__device__ int    d_bsum[NBLK];
__device__ int    d_boff[NBLK];
__device__ int    d_arr;
__device__ volatile int d_flag;               // monotonically increasing epoch

// ---------------- helpers ----------------
__device__ __forceinline__ float softplusf(float x) {
    return fmaxf(x, 0.0f) + log1pf(expf(-fabsf(x)));
}

__device__ __forceinline__ void mma_f16(float c[4], const uint32_t a[4],
                                        uint32_t b0, uint32_t b1) {
    asm volatile(
        "mma.sync.aligned.m16n8k16.row.col.f32.f16.f16.f32 "
        "{%0,%1,%2,%3}, {%4,%5,%6,%7}, {%8,%9}, {%0,%1,%2,%3};\n"
        : "+f"(c[0]), "+f"(c[1]), "+f"(c[2]), "+f"(c[3])
        : "r"(a[0]), "r"(a[1]), "r"(a[2]), "r"(a[3]), "r"(b0), "r"(b1));
}

__device__ __forceinline__ void cp_async16(uint32_t smem_dst, const void* gsrc) {
    asm volatile("cp.async.cg.shared.global [%0], [%1], 16;\n"
                 :: "r"(smem_dst), "l"(gsrc) : "memory");
}
__device__ __forceinline__ void cp_async16p(uint32_t smem_dst, const void* gsrc, int src_bytes) {
    asm volatile("cp.async.cg.shared.global [%0], [%1], 16, %2;\n"
                 :: "r"(smem_dst), "l"(gsrc), "r"(src_bytes) : "memory");
}
__device__ __forceinline__ void cp_commit() {
    asm volatile("cp.async.commit_group;\n" ::: "memory");
}
template <int N>
__device__ __forceinline__ void cp_wait() {
    asm volatile("cp.async.wait_group %0;\n" :: "n"(N) : "memory");
}

__device__ __forceinline__ uint4 pack8(float4 f0, float4 f1) {
    __half2 h0 = __float22half2_rn(make_float2(f0.x, f0.y));
    __half2 h1 = __float22half2_rn(make_float2(f0.z, f0.w));
    __half2 h2 = __float22half2_rn(make_float2(f1.x, f1.y));
    __half2 h3 = __float22half2_rn(make_float2(f1.z, f1.w));
    uint4 u;
    u.x = *(uint32_t*)&h0; u.y = *(uint32_t*)&h1;
    u.z = *(uint32_t*)&h2; u.w = *(uint32_t*)&h3;
    return u;
}

// ---------------- weight conversion: W0 -> fp16, W1 -> fp16 padded ----------------
__global__ void k_initW(const float* __restrict__ W0, const float* __restrict__ W1) {
    int i = blockIdx.x * blockDim.x + threadIdx.x;
    if (i < HD1 * HD2P) {
        int k = i / HD2P, n = i % HD2P;
        d_W1h[i] = __float2half((n < HD2R) ? W1[k * HD2R + n] : 0.0f);
    }
    if (i < W0CHUNKS) {
        const float4* p = (const float4*)W0 + (size_t)i * 2;
        ((uint4*)d_W0h)[i] = pack8(p[0], p[1]);
    }
}

// ---------------- CSR build ----------------
__global__ void k_hist(const int4* __restrict__ dst4) {
    int e = blockIdx.x * blockDim.x + threadIdx.x;
    if (e < NE / 4) {
        int4 d = dst4[e];
        atomicAdd(&d_cnt[d.x], 1);
        atomicAdd(&d_cnt[d.y], 1);
        atomicAdd(&d_cnt[d.z], 1);
        atomicAdd(&d_cnt[d.w], 1);
    }
}

// Fused scan: per-block inclusive scan + single grid sync (atomic arrival +
// epoch flag) + global offset apply. All NBLK=98 blocks are co-resident
// (98 < 148 SMs), so the spin cannot deadlock. Deterministic across replays.
__global__ void __launch_bounds__(SCAN_B)
k_scanfuse() {
    __shared__ int sh[SCAN_B];
    __shared__ int sb[128];
    __shared__ int isLast;
    const int t = threadIdx.x, b = blockIdx.x;
    const int epoch = d_flag;          // volatile read BEFORE arrival
    const int i = b * SCAN_B + t;
    const int v = (i < NN) ? d_cnt[i] : 0;
    sh[t] = v;
    __syncthreads();
    for (int off = 1; off < SCAN_B; off <<= 1) {
        int add = (t >= off) ? sh[t - off] : 0;
        __syncthreads();
        sh[t] += add;
        __syncthreads();
    }
    const int incl = sh[t];
    if (t == SCAN_B - 1) d_bsum[b] = incl;     // block total
    __threadfence();
    if (t == 0) {
        int old = atomicAdd(&d_arr, 1);
        isLast = (old == NBLK - 1) ? 1 : 0;
    }
    __syncthreads();
    if (isLast) {
        __threadfence();                       // all producers' bsum visible
        int vv = (t < NBLK) ? d_bsum[t] : 0;
        if (t < 128) sb[t] = vv;
        __syncthreads();
        for (int off = 1; off < 128; off <<= 1) {
            int add = (t < 128 && t >= off) ? sb[t - off] : 0;
            __syncthreads();
            if (t < 128) sb[t] += add;
            __syncthreads();
        }
        if (t < NBLK) d_boff[t] = sb[t] - vv;  // exclusive
        if (t == 0) d_arr = 0;                 // restore invariant
        __threadfence();
        __syncthreads();
        if (t == 0) d_flag = epoch + 1;        // release
    } else {
        if (t == 0) { while (d_flag == epoch) { } }
        __syncthreads();
        __threadfence();                       // acquire d_boff
    }
    if (i < NN) {
        int base = d_boff[b] + incl - v;
        d_rp[i] = base;
        d_cur[i] = base;
        d_dinv[i] = rsqrtf((float)v + 1.0f);
        d_cnt[i] = 0;                          // restore zero invariant
        if (i == NN - 1) d_rp[NN] = d_boff[b] + incl;
    }
}

__global__ void k_fill(const int4* __restrict__ src4, const int4* __restrict__ dst4) {
    int e = blockIdx.x * blockDim.x + threadIdx.x;
    if (e >= NE / 4) return;
    int4 s = src4[e];
    int4 d = dst4[e];
    d_col[atomicAdd(&d_cur[d.x], 1)] = s.x;
    d_col[atomicAdd(&d_cur[d.y], 1)] = s.y;
    d_col[atomicAdd(&d_cur[d.z], 1)] = s.z;
    d_col[atomicAdd(&d_cur[d.w], 1)] = s.w;
}

// ---------------- GEMM1: fused fp32->fp16 A, cp.async 3-stage, 128x128 tile --------
#define CF_A32SZ 18432
#define CF_B16SZ 8704
#define CF_A16SZ 10240
#define CF_SMEM  (3 * CF_A32SZ + 3 * CF_B16SZ + 2 * CF_A16SZ)

__global__ void __launch_bounds__(256, 2)
k_gemm_cf(const float* __restrict__ Ag, const __half* __restrict__ Bg,
          __half* __restrict__ Cg) {
    extern __shared__ char dsm[];
    const int tid = threadIdx.x;
    const int warp = tid >> 5, lane = tid & 31;
    const int wm = warp >> 2, wn = warp & 3;
    const int g = lane >> 2, t = lane & 3;
    const int bm = blockIdx.y * 128, bn = blockIdx.x * 128;

    const int l8 = lane & 7;
    const int lm8 = (lane >> 3) & 1;
    const int lk8 = lane >> 4;
    const int arow_off = l8 + (lm8 << 3);

    const uint32_t smb = (uint32_t)__cvta_generic_to_shared(dsm);
    const uint32_t a32b = smb;
    const uint32_t b16b = smb + 3 * CF_A32SZ;
    const uint32_t a16b = b16b + 3 * CF_B16SZ;

    char* const a32g = dsm;
    char* const a16g = dsm + 3 * CF_A32SZ + 3 * CF_B16SZ;

    float acc[4][4][4];
#pragma unroll
    for (int mt = 0; mt < 4; mt++)
#pragma unroll
        for (int nt = 0; nt < 4; nt++)
#pragma unroll
            for (int j = 0; j < 4; j++) acc[mt][nt][j] = 0.0f;

    auto issue = [&](int it) {
        const int k0 = it << 5;
        const uint32_t sa = a32b + (uint32_t)(it % 3) * CF_A32SZ;
        const uint32_t sb = b16b + (uint32_t)(it % 3) * CF_B16SZ;
#pragma unroll
        for (int i = 0; i < 4; i++) {
            int idx = tid + 256 * i;
            int r = idx >> 3, c = (idx & 7) << 2;
            int gr = bm + r;
            int cr = (gr < NN) ? gr : (NN - 1);
            cp_async16p(sa + (uint32_t)(r * 36 + c) * 4u,
                        Ag + (size_t)cr * INDIM + k0 + c, (gr < NN) ? 16 : 0);
        }
#pragma unroll
        for (int i = 0; i < 2; i++) {
            int idx = tid + 256 * i;
            int r = idx >> 4, ch = (idx & 15) << 3;
            cp_async16(sb + (uint32_t)(r * 136 + ch) * 2u,
                       Bg + (size_t)(k0 + r) * HD1 + bn + ch);
        }
        cp_commit();
    };

    issue(0);
    issue(1);

    const int nIter = INDIM >> 5;   // 16
    for (int it = 0; it < nIter; it++) {
        cp_wait<1>();
        __syncthreads();

        {
            char* s32 = a32g + (it % 3) * CF_A32SZ;
            char* d16 = a16g + (it & 1) * CF_A16SZ;
#pragma unroll
            for (int i = 0; i < 4; i++) {
                int idx = tid + 256 * i;
                int r = idx >> 3, c = (idx & 7) << 2;
                float4 v = *(const float4*)(s32 + (r * 36 + c) * 4);
                __half2 h0 = __float22half2_rn(make_float2(v.x, v.y));
                __half2 h1 = __float22half2_rn(make_float2(v.z, v.w));
                uint2 u;
                u.x = *(uint32_t*)&h0;
                u.y = *(uint32_t*)&h1;
                *(uint2*)(d16 + (r * 40 + c) * 2) = u;
            }
        }
        __syncthreads();

        if (it + 2 < nIter) issue(it + 2);

        const uint32_t as_b = a16b + (uint32_t)(it & 1) * CF_A16SZ;
        const uint32_t bs_b = b16b + (uint32_t)(it % 3) * CF_B16SZ;
#pragma unroll
        for (int kk = 0; kk < 2; kk++) {
            uint32_t a[4][4], b[2][4];
            const int acol = (kk << 4) + (lk8 << 3);
#pragma unroll
            for (int mt = 0; mt < 4; mt++) {
                int row = wm * 64 + mt * 16 + arow_off;
                uint32_t addr = as_b + (uint32_t)(row * 40 + acol) * 2u;
                asm volatile(
                    "ldmatrix.sync.aligned.m8n8.x4.shared.b16 {%0,%1,%2,%3}, [%4];"
                    : "=r"(a[mt][0]), "=r"(a[mt][1]), "=r"(a[mt][2]), "=r"(a[mt][3])
                    : "r"(addr));
            }
            const int brow = (kk << 4) + arow_off;
#pragma unroll
            for (int h = 0; h < 2; h++) {
                int ncol = wn * 32 + (h << 4) + (lk8 << 3);
                uint32_t addr = bs_b + (uint32_t)(brow * 136 + ncol) * 2u;
                asm volatile(
                    "ldmatrix.sync.aligned.m8n8.x4.trans.shared.b16 {%0,%1,%2,%3}, [%4];"
                    : "=r"(b[h][0]), "=r"(b[h][1]), "=r"(b[h][2]), "=r"(b[h][3])
                    : "r"(addr));
            }
#pragma unroll
            for (int mt = 0; mt < 4; mt++)
#pragma unroll
                for (int nt = 0; nt < 4; nt++)
                    mma_f16(acc[mt][nt], a[mt],
                            b[nt >> 1][(nt & 1) * 2], b[nt >> 1][(nt & 1) * 2 + 1]);
        }
    }

#pragma unroll
    for (int mt = 0; mt < 4; mt++) {
        int r0 = bm + wm * 64 + mt * 16 + g;
        int r1 = r0 + 8;
#pragma unroll
        for (int nt = 0; nt < 4; nt++) {
            int c = bn + wn * 32 + nt * 8 + t * 2;
            if (r0 < NN)
                *(__half2*)(Cg + (size_t)r0 * HD1 + c) =
                    __float22half2_rn(make_float2(acc[mt][nt][0], acc[mt][nt][1]));
            if (r1 < NN)
                *(__half2*)(Cg + (size_t)r1 * HD1 + c) =
                    __float22half2_rn(make_float2(acc[mt][nt][2], acc[mt][nt][3]));
        }
    }
}

// ---------------- cp.async fp16 GEMM (GEMM2): 128x64 tile, BK=32, 3 stages ----------
template <int BN>
__global__ void __launch_bounds__(256, 2)
k_gemm_cp(const __half* __restrict__ Ag, const __half* __restrict__ Bg,
          __half* __restrict__ Cg, int M, int N, int K,
          int lda, int ldb, int ldc) {
    constexpr int NT = BN / 32;
    constexpr int SA = 40;
    constexpr int SB = BN + 8;
    constexpr int ASZ = 128 * SA * 2;
    constexpr int BSZ = 32 * SB * 2;
    constexpr int STAGES = 3;

    extern __shared__ char dsm[];

    const int tid = threadIdx.x;
    const int warp = tid >> 5, lane = tid & 31;
    const int wm = warp >> 2, wn = warp & 3;
    const int g = lane >> 2, t = lane & 3;
    const int bm = blockIdx.y * 128, bn = blockIdx.x * BN;

    const int l8 = lane & 7;
    const int lm8 = (lane >> 3) & 1;
    const int lk8 = lane >> 4;
    const int arow_off = l8 + (lm8 << 3);

    uint32_t sbase[STAGES];
#pragma unroll
    for (int s = 0; s < STAGES; s++)
        sbase[s] = (uint32_t)__cvta_generic_to_shared(dsm + s * (ASZ + BSZ));

    float acc[4][NT][4];
#pragma unroll
    for (int mt = 0; mt < 4; mt++)
#pragma unroll
        for (int nt = 0; nt < NT; nt++)
#pragma unroll
            for (int j = 0; j < 4; j++) acc[mt][nt][j] = 0.0f;

    const int nIter = K >> 5;

    auto issue = [&](int it) {
        const int k0 = it << 5;
        const uint32_t sa = sbase[it % STAGES];
        const uint32_t sb = sa + ASZ;
#pragma unroll
        for (int i = 0; i < 2; i++) {
            int idx = tid + 256 * i;
            int r = idx >> 2, ch = (idx & 3) << 3;
            int gr = bm + r;
            int cr = (gr < M) ? gr : (M - 1);
            const __half* src = Ag + (size_t)cr * lda + k0 + ch;
            cp_async16p(sa + (uint32_t)(r * SA + ch) * 2u, src, (gr < M) ? 16 : 0);
        }
        {
            int r = tid >> 3, ch = (tid & 7) << 3;
            int gc = bn + ch;
            int cc = (gc < N) ? gc : 0;
            const __half* src = Bg + (size_t)(k0 + r) * ldb + cc;
            cp_async16p(sb + (uint32_t)(r * SB + ch) * 2u, src, (gc < N) ? 16 : 0);
        }
        cp_commit();
    };

    issue(0);
    if (nIter > 1) issue(1); else cp_commit();

    for (int it = 0; it < nIter; it++) {
        cp_wait<1>();
        __syncthreads();
        if (it + 2 < nIter) issue(it + 2);

        const uint32_t as_b = sbase[it % STAGES];
        const uint32_t bs_b = as_b + ASZ;
#pragma unroll
        for (int kk = 0; kk < 2; kk++) {
            uint32_t a[4][4], b[NT / 2][4];
            const int acol = (kk << 4) + (lk8 << 3);
#pragma unroll
            for (int mt = 0; mt < 4; mt++) {
                int rw = wm * 64 + mt * 16 + arow_off;
                uint32_t addr = as_b + (uint32_t)(rw * SA + acol) * 2u;
                asm volatile(
                    "ldmatrix.sync.aligned.m8n8.x4.shared.b16 {%0,%1,%2,%3}, [%4];"
                    : "=r"(a[mt][0]), "=r"(a[mt][1]), "=r"(a[mt][2]), "=r"(a[mt][3])
                    : "r"(addr));
            }
            const int brow = (kk << 4) + arow_off;
#pragma unroll
            for (int h = 0; h < NT / 2; h++) {
                int ncol = wn * (NT * 8) + (h << 4) + (lk8 << 3);
                uint32_t addr = bs_b + (uint32_t)(brow * SB + ncol) * 2u;
                asm volatile(
                    "ldmatrix.sync.aligned.m8n8.x4.trans.shared.b16 {%0,%1,%2,%3}, [%4];"
                    : "=r"(b[h][0]), "=r"(b[h][1]), "=r"(b[h][2]), "=r"(b[h][3])
                    : "r"(addr));
            }
#pragma unroll
            for (int mt = 0; mt < 4; mt++)
#pragma unroll
                for (int nt = 0; nt < NT; nt++)
                    mma_f16(acc[mt][nt], a[mt],
                            b[nt >> 1][(nt & 1) * 2], b[nt >> 1][(nt & 1) * 2 + 1]);
        }
        __syncthreads();
    }

#pragma unroll
    for (int mt = 0; mt < 4; mt++) {
        int r0 = bm + wm * 64 + mt * 16 + g;
        int r1 = r0 + 8;
#pragma unroll
        for (int nt = 0; nt < NT; nt++) {
            int c = bn + wn * (NT * 8) + nt * 8 + t * 2;
            if (c < N) {
                if (r0 < M)
                    *(__half2*)(Cg + (size_t)r0 * ldc + c) =
                        __float22half2_rn(make_float2(acc[mt][nt][0], acc[mt][nt][1]));
                if (r1 < M)
                    *(__half2*)(Cg + (size_t)r1 * ldc + c) =
                        __float22half2_rn(make_float2(acc[mt][nt][2], acc[mt][nt][3]));
            }
        }
    }
}

// ---------------- GEMV for layer-2 column 128 (kappa pre-activation) ----------------
// H2[:,128] = HB(50000x256 fp16) . W1[:,128] (fp32, read straight from input W1)
__global__ void __launch_bounds__(256)
k_gemv128(const float* __restrict__ W1) {
    int node = blockIdx.x * 8 + (threadIdx.x >> 5);
    int lane = threadIdx.x & 31;
    const __half* hb = d_HB + (size_t)node * HD1 + lane * 8;
    uint4 u = *(const uint4*)hb;
    const __half2* h2 = (const __half2*)&u;
    float s = 0.0f;
#pragma unroll
    for (int j = 0; j < 4; j++) {
        float2 f = __half22float2(h2[j]);
        int k = lane * 8 + 2 * j;
        s += f.x * __ldg(&W1[(size_t)k * HD2R + 128])
           + f.y * __ldg(&W1[(size_t)(k + 1) * HD2R + 128]);
    }
#pragma unroll
    for (int off = 16; off; off >>= 1) s += __shfl_down_sync(0xffffffffu, s, off);
    if (lane == 0) d_HAh[(size_t)node * HD2P + 128] = __float2half(s);
}

// ---------------- aggregation layer 1: fp16 gather, 32 lanes/node -> fp16 out ----------------
__global__ void __launch_bounds__(256)
k_agg1() {
    int node = blockIdx.x * 8 + (threadIdx.x >> 5);
    int lane = threadIdx.x & 31;
    const __half* H = d_HAh;
    float di = d_dinv[node];
    float sw = di * di;

    const int coff = lane * 8;
    float acc[8];
    {
        uint4 u = *(const uint4*)(H + (size_t)node * HD1 + coff);
        const __half2* h2 = (const __half2*)&u;
#pragma unroll
        for (int j = 0; j < 4; j++) {
            float2 f = __half22float2(h2[j]);
            acc[2 * j] = f.x * sw;
            acc[2 * j + 1] = f.y * sw;
        }
    }

    int e = d_rp[node], e1 = d_rp[node + 1];
    while (e < e1 && (e & 3)) {
        int s0 = d_col[e];
        float w0 = di * d_dinv[s0];
        uint4 u0 = *(const uint4*)(H + (size_t)s0 * HD1 + coff);
        const __half2* a0 = (const __half2*)&u0;
#pragma unroll
        for (int j = 0; j < 4; j++) {
            float2 f0 = __half22float2(a0[j]);
            acc[2 * j]     += f0.x * w0;
            acc[2 * j + 1] += f0.y * w0;
        }
        e++;
    }
    for (; e + 3 < e1; e += 4) {
        int4 cc = *(const int4*)&d_col[e];
        float w0 = di * d_dinv[cc.x];
        float w1 = di * d_dinv[cc.y];
        float w2 = di * d_dinv[cc.z];
        float w3 = di * d_dinv[cc.w];
        uint4 u0 = *(const uint4*)(H + (size_t)cc.x * HD1 + coff);
        uint4 u1 = *(const uint4*)(H + (size_t)cc.y * HD1 + coff);
        uint4 u2 = *(const uint4*)(H + (size_t)cc.z * HD1 + coff);
        uint4 u3 = *(const uint4*)(H + (size_t)cc.w * HD1 + coff);
        const __half2* a0 = (const __half2*)&u0;
        const __half2* a1 = (const __half2*)&u1;
        const __half2* a2 = (const __half2*)&u2;
        const __half2* a3 = (const __half2*)&u3;
#pragma unroll
        for (int j = 0; j < 4; j++) {
            float2 f0 = __half22float2(a0[j]);
            float2 f1 = __half22float2(a1[j]);
            float2 f2 = __half22float2(a2[j]);
            float2 f3 = __half22float2(a3[j]);
            acc[2 * j]     += f0.x * w0 + f1.x * w1 + f2.x * w2 + f3.x * w3;
            acc[2 * j + 1] += f0.y * w0 + f1.y * w1 + f2.y * w2 + f3.y * w3;
        }
    }
    for (; e < e1; e++) {
        int s0 = d_col[e];
        float w0 = di * d_dinv[s0];
        uint4 u0 = *(const uint4*)(H + (size_t)s0 * HD1 + coff);
        const __half2* a0 = (const __half2*)&u0;
#pragma unroll
        for (int j = 0; j < 4; j++) {
            float2 f0 = __half22float2(a0[j]);
            acc[2 * j]     += f0.x * w0;
            acc[2 * j + 1] += f0.y * w0;
        }
    }

    __half* outp = d_HB + (size_t)node * HD1 + coff;
    __half2 p0 = __float22half2_rn(make_float2(softplusf(acc[0]), softplusf(acc[1])));
    __half2 p1 = __float22half2_rn(make_float2(softplusf(acc[2]), softplusf(acc[3])));
    __half2 p2 = __float22half2_rn(make_float2(softplusf(acc[4]), softplusf(acc[5])));
    __half2 p3 = __float22half2_rn(make_float2(softplusf(acc[6]), softplusf(acc[7])));
    uint4 st;
    st.x = *(uint32_t*)&p0;
    st.y = *(uint32_t*)&p1;
    st.z = *(uint32_t*)&p2;
    st.w = *(uint32_t*)&p3;
    *(uint4*)outp = st;
}

// ---------------- aggregation layer 2 + epilogue: fp16 gather, 16 lanes/node ----------------
__global__ void __launch_bounds__(256)
k_agg2(float* __restrict__ out) {
    int node = blockIdx.x * 16 + (threadIdx.x >> 4);
    int lane = threadIdx.x & 15;
    const __half* H = d_HAh;
    float di = d_dinv[node];
    float sw = di * di;

    const int coff = lane * 8;
    const __half* srow = H + (size_t)node * HD2P;
    float acc[8];
    {
        uint4 u = *(const uint4*)(srow + coff);
        const __half2* h2 = (const __half2*)&u;
#pragma unroll
        for (int j = 0; j < 4; j++) {
            float2 f = __half22float2(h2[j]);
            acc[2 * j] = f.x * sw;
            acc[2 * j + 1] = f.y * sw;
        }
    }
    float acck = (lane == 0) ? __half2float(srow[128]) * sw : 0.0f;

    int e = d_rp[node], e1 = d_rp[node + 1];
    for (; e + 3 < e1; e += 4) {
        int s0 = d_col[e], s1 = d_col[e + 1], s2 = d_col[e + 2], s3 = d_col[e + 3];
        float w0 = di * d_dinv[s0];
        float w1 = di * d_dinv[s1];
        float w2 = di * d_dinv[s2];
        float w3 = di * d_dinv[s3];
        const __half* r0 = H + (size_t)s0 * HD2P;
        const __half* r1 = H + (size_t)s1 * HD2P;
        const __half* r2 = H + (size_t)s2 * HD2P;
        const __half* r3 = H + (size_t)s3 * HD2P;
        uint4 u0 = *(const uint4*)(r0 + coff);
        uint4 u1 = *(const uint4*)(r1 + coff);
        uint4 u2 = *(const uint4*)(r2 + coff);
        uint4 u3 = *(const uint4*)(r3 + coff);
        const __half2* a0 = (const __half2*)&u0;
        const __half2* a1 = (const __half2*)&u1;
        const __half2* a2 = (const __half2*)&u2;
        const __half2* a3 = (const __half2*)&u3;
#pragma unroll
        for (int j = 0; j < 4; j++) {
            float2 f0 = __half22float2(a0[j]);
            float2 f1 = __half22float2(a1[j]);
            float2 f2 = __half22float2(a2[j]);
            float2 f3 = __half22float2(a3[j]);
            acc[2 * j]     += f0.x * w0 + f1.x * w1 + f2.x * w2 + f3.x * w3;
            acc[2 * j + 1] += f0.y * w0 + f1.y * w1 + f2.y * w2 + f3.y * w3;
        }
        if (lane == 0)
            acck += __half2float(r0[128]) * w0 + __half2float(r1[128]) * w1
                  + __half2float(r2[128]) * w2 + __half2float(r3[128]) * w3;
    }
    for (; e < e1; e++) {
        int s0 = d_col[e];
        float w0 = di * d_dinv[s0];
        const __half* r0 = H + (size_t)s0 * HD2P;
        uint4 u0 = *(const uint4*)(r0 + coff);
        const __half2* a0 = (const __half2*)&u0;
#pragma unroll
        for (int j = 0; j < 4; j++) {
            float2 f0 = __half22float2(a0[j]);
            acc[2 * j]     += f0.x * w0;
            acc[2 * j + 1] += f0.y * w0;
        }
        if (lane == 0) acck += __half2float(r0[128]) * w0;
    }

    float lbd[8];
#pragma unroll
    for (int j = 0; j < 8; j++) lbd[j] = softplusf(acc[j]);

    float g = 0.0f, kap = 0.0f;
    if (lane == 0) {
        kap = softplusf(acck) + 0.1f;
        g = expf(lgammaf(1.0f + 1.0f / kap));
    }
    g = __shfl_sync(0xffffffffu, g, (threadIdx.x & 16), 32);

    const size_t ZOFF = 0;
    const size_t LOFF = (size_t)NN * 128;
    const size_t KOFF = (size_t)NN * 256;

    float* zp = out + ZOFF + (size_t)node * 128 + coff;
    float* lp = out + LOFF + (size_t)node * 128 + coff;
    *(float4*)zp       = make_float4(lbd[0] * g, lbd[1] * g, lbd[2] * g, lbd[3] * g);
    *(float4*)(zp + 4) = make_float4(lbd[4] * g, lbd[5] * g, lbd[6] * g, lbd[7] * g);
    *(float4*)lp       = make_float4(lbd[0], lbd[1], lbd[2], lbd[3]);
    *(float4*)(lp + 4) = make_float4(lbd[4], lbd[5], lbd[6], lbd[7]);
    if (lane == 0) out[KOFF + node] = kap;
}

// ---------------- launch ----------------
extern "C" void kernel_launch(void* const* d_in, const int* in_sizes, int n_in,
                              void* d_out, int out_size) {
    const float* x  = (const float*)d_in[0];
    const int* eidx = (const int*)d_in[1];
    const float* W0 = (const float*)d_in[2];
    const float* W1 = (const float*)d_in[3];
    float* out = (float*)d_out;

    const int4* src4 = (const int4*)eidx;
    const int4* dst4 = (const int4*)(eidx + NE);

    __half* W0h; cudaGetSymbolAddress((void**)&W0h, d_W0h);
    __half* W1h; cudaGetSymbolAddress((void**)&W1h, d_W1h);
    __half* HAh; cudaGetSymbolAddress((void**)&HAh, d_HAh);
    __half* HB;  cudaGetSymbolAddress((void**)&HB, d_HB);

    const int smem64 = 3 * (10240 + 32 * (64 + 8) * 2);
    cudaFuncSetAttribute(k_gemm_cp<64>, cudaFuncAttributeMaxDynamicSharedMemorySize, smem64);
    cudaFuncSetAttribute(k_gemm_cf, cudaFuncAttributeMaxDynamicSharedMemorySize, CF_SMEM);

    // Side stream + events (capture-legal fork/join, proven R6-R12).
    cudaStream_t s1;
    cudaStreamCreateWithFlags(&s1, cudaStreamNonBlocking);
    cudaEvent_t ef, ej, e1, e2;
    cudaEventCreateWithFlags(&ef, cudaEventDisableTiming);
    cudaEventCreateWithFlags(&ej, cudaEventDisableTiming);
    cudaEventCreateWithFlags(&e1, cudaEventDisableTiming);
    cudaEventCreateWithFlags(&e2, cudaEventDisableTiming);

    cudaEventRecord(ef, 0);
    cudaStreamWaitEvent(s1, ef, 0);

    // main: W0/W1 -> fp16 (submission 0)
    k_initW<<<(INITW_N + 255) / 256, 256>>>(W0, W1);

    // side: CSR — hist (d_cnt zero by invariant), fused scan (submissions 1,2)
    k_hist<<<(NE / 4 + 255) / 256, 256, 0, s1>>>(dst4);
    k_scanfuse<<<NBLK, SCAN_B, 0, s1>>>();

    // main: GEMM1 fused-convert (submission 3 — ncu capture slot)
    {
        dim3 grid(2, (NN + 127) / 128);
        k_gemm_cf<<<grid, 256, CF_SMEM>>>(x, W0h, HAh);
    }

    // side: fill (overlaps GEMM1)
    k_fill<<<(NE / 4 + 255) / 256, 256, 0, s1>>>(src4, dst4);
    cudaEventRecord(ej, s1);

    // join: agg1 needs GEMM1 + CSR
    cudaStreamWaitEvent(0, ej, 0);

    // AGG1 + softplus -> HB (fp16)
    k_agg1<<<NN / 8, 256>>>();
    cudaEventRecord(e1, 0);

    // side: GEMV for column 128 (concurrent with GEMM2; BW-bound vs tensor-bound)
    cudaStreamWaitEvent(s1, e1, 0);
    k_gemv128<<<NN / 8, 256, 0, s1>>>(W1);
    cudaEventRecord(e2, s1);

    // main: GEMM2 cols 0..127 only: HAh(stride 136) = HB @ W1h, BN=64 x 2
    {
        dim3 grid(2, (NN + 127) / 128);
        k_gemm_cp<64><<<grid, 256, smem64>>>(HB, W1h, HAh, NN, 128, HD1,
                                             HD1, HD2P, HD2P);
    }
    cudaStreamWaitEvent(0, e2, 0);

    // AGG2 + softplus + Weibull epilogue -> out
    k_agg2<<<NN / 16, 256>>>(out);
}

// round 16
// speedup vs baseline: 1.0083x; 1.0083x over previous
#include <cuda_runtime.h>
#include <cuda_fp16.h>
#include <math.h>
#include <stdint.h>

// Problem constants
#define NN    50000
#define NE    1600000
#define INDIM 512
#define HD1   256
#define HD2R  129     // real cols of layer 2
#define HD2P  136     // padded stride in halves (272B, 16B-aligned)

#define SCAN_B 512
#define NBLK   ((NN + SCAN_B - 1) / SCAN_B)   // 98

#define W0CHUNKS (INDIM * HD1 / 8)      // 16384
#define INITW_N  (HD1 * HD2P)           // 34816 (> W0CHUNKS)

// ---------------- static scratch (no allocations allowed) ----------------
// d_cnt invariant: zero at module load; k_local re-zeroes it after use, so
// every kernel_launch call (and every graph replay) sees d_cnt == 0.
__device__ __half d_W0h[INDIM * HD1];         // fp16 W0 [K=512][N=256]
__device__ __half d_W1h[HD1 * HD2P];          // fp16 W1, padded
__device__ __half d_HAh[(size_t)NN * HD1];    // fp16 XW0; reused as H1W1 (stride HD2P)
__device__ __half d_HB[(size_t)NN * HD1];     // fp16 softplus(agg1)
__device__ int    d_col[NE];
__device__ int    d_rp[NN + 1];
__device__ int    d_cur[NN];
__device__ int    d_cnt[NN];
__device__ float  d_dinv[NN];
__device__ int    d_bsum[NBLK];
__device__ int    d_boff[NBLK];

// ---------------- helpers ----------------
__device__ __forceinline__ float softplusf(float x) {
    return fmaxf(x, 0.0f) + log1pf(expf(-fabsf(x)));
}

__device__ __forceinline__ void mma_f16(float c[4], const uint32_t a[4],
                                        uint32_t b0, uint32_t b1) {
    asm volatile(
        "mma.sync.aligned.m16n8k16.row.col.f32.f16.f16.f32 "
        "{%0,%1,%2,%3}, {%4,%5,%6,%7}, {%8,%9}, {%0,%1,%2,%3};\n"
        : "+f"(c[0]), "+f"(c[1]), "+f"(c[2]), "+f"(c[3])
        : "r"(a[0]), "r"(a[1]), "r"(a[2]), "r"(a[3]), "r"(b0), "r"(b1));
}

__device__ __forceinline__ void cp_async16(uint32_t smem_dst, const void* gsrc) {
    asm volatile("cp.async.cg.shared.global [%0], [%1], 16;\n"
                 :: "r"(smem_dst), "l"(gsrc) : "memory");
}
__device__ __forceinline__ void cp_async16p(uint32_t smem_dst, const void* gsrc, int src_bytes) {
    asm volatile("cp.async.cg.shared.global [%0], [%1], 16, %2;\n"
                 :: "r"(smem_dst), "l"(gsrc), "r"(src_bytes) : "memory");
}
__device__ __forceinline__ void cp_commit() {
    asm volatile("cp.async.commit_group;\n" ::: "memory");
}
template <int N>
__device__ __forceinline__ void cp_wait() {
    asm volatile("cp.async.wait_group %0;\n" :: "n"(N) : "memory");
}

__device__ __forceinline__ uint4 pack8(float4 f0, float4 f1) {
    __half2 h0 = __float22half2_rn(make_float2(f0.x, f0.y));
    __half2 h1 = __float22half2_rn(make_float2(f0.z, f0.w));
    __half2 h2 = __float22half2_rn(make_float2(f1.x, f1.y));
    __half2 h3 = __float22half2_rn(make_float2(f1.z, f1.w));
    uint4 u;
    u.x = *(uint32_t*)&h0; u.y = *(uint32_t*)&h1;
    u.z = *(uint32_t*)&h2; u.w = *(uint32_t*)&h3;
    return u;
}

// accumulate one gathered fp16 row-chunk into acc[8]
__device__ __forceinline__ void acc8(float acc[8], const uint4& u, float w) {
    const __half2* a = (const __half2*)&u;
#pragma unroll
    for (int j = 0; j < 4; j++) {
        float2 f = __half22float2(a[j]);
        acc[2 * j]     += f.x * w;
        acc[2 * j + 1] += f.y * w;
    }
}

// ---------------- weight conversion: W0 -> fp16, W1 -> fp16 padded ----------------
__global__ void k_initW(const float* __restrict__ W0, const float* __restrict__ W1) {
    int i = blockIdx.x * blockDim.x + threadIdx.x;
    if (i < HD1 * HD2P) {
        int k = i / HD2P, n = i % HD2P;
        d_W1h[i] = __float2half((n < HD2R) ? W1[k * HD2R + n] : 0.0f);
    }
    if (i < W0CHUNKS) {
        const float4* p = (const float4*)W0 + (size_t)i * 2;
        ((uint4*)d_W0h)[i] = pack8(p[0], p[1]);
    }
}

// ---------------- CSR build ----------------
__global__ void k_hist(const int4* __restrict__ dst4) {
    int e = blockIdx.x * blockDim.x + threadIdx.x;
    if (e < NE / 4) {
        int4 d = dst4[e];
        atomicAdd(&d_cnt[d.x], 1);
        atomicAdd(&d_cnt[d.y], 1);
        atomicAdd(&d_cnt[d.z], 1);
        atomicAdd(&d_cnt[d.w], 1);
    }
}

__global__ void k_blocksum() {
    __shared__ int sh[SCAN_B];
    int t = threadIdx.x;
    int i = blockIdx.x * SCAN_B + t;
    sh[t] = (i < NN) ? d_cnt[i] : 0;
    __syncthreads();
    for (int off = SCAN_B / 2; off > 0; off >>= 1) {
        if (t < off) sh[t] += sh[t + off];
        __syncthreads();
    }
    if (t == 0) d_bsum[blockIdx.x] = sh[0];
}

__global__ void k_bscan() {
    __shared__ int sh[128];
    int t = threadIdx.x;
    int v = (t < NBLK) ? d_bsum[t] : 0;
    sh[t] = v;
    __syncthreads();
    for (int off = 1; off < 128; off <<= 1) {
        int add = (t >= off) ? sh[t - off] : 0;
        __syncthreads();
        sh[t] += add;
        __syncthreads();
    }
    if (t < NBLK) d_boff[t] = sh[t] - v;
}

__global__ void k_local() {
    __shared__ int sh[SCAN_B];
    int t = threadIdx.x;
    int i = blockIdx.x * SCAN_B + t;
    int v = (i < NN) ? d_cnt[i] : 0;
    sh[t] = v;
    __syncthreads();
    for (int off = 1; off < SCAN_B; off <<= 1) {
        int add = (t >= off) ? sh[t - off] : 0;
        __syncthreads();
        sh[t] += add;
        __syncthreads();
    }
    if (i < NN) {
        int incl = sh[t];
        int base = d_boff[blockIdx.x] + incl - v;
        d_rp[i] = base;
        d_cur[i] = base;
        d_dinv[i] = rsqrtf((float)v + 1.0f);
        d_cnt[i] = 0;   // restore zero invariant for the next launch/replay
        if (i == NN - 1) d_rp[NN] = d_boff[blockIdx.x] + incl;
    }
}

__global__ void k_fill(const int4* __restrict__ src4, const int4* __restrict__ dst4) {
    int e = blockIdx.x * blockDim.x + threadIdx.x;
    if (e >= NE / 4) return;
    int4 s = src4[e];
    int4 d = dst4[e];
    d_col[atomicAdd(&d_cur[d.x], 1)] = s.x;
    d_col[atomicAdd(&d_cur[d.y], 1)] = s.y;
    d_col[atomicAdd(&d_cur[d.z], 1)] = s.z;
    d_col[atomicAdd(&d_cur[d.w], 1)] = s.w;
}

// ---------------- GEMM1: fused fp32->fp16 A, cp.async 3-stage, 128x128 tile --------
#define CF_A32SZ 18432
#define CF_B16SZ 8704
#define CF_A16SZ 10240
#define CF_SMEM  (3 * CF_A32SZ + 3 * CF_B16SZ + 2 * CF_A16SZ)

__global__ void __launch_bounds__(256, 2)
k_gemm_cf(const float* __restrict__ Ag, const __half* __restrict__ Bg,
          __half* __restrict__ Cg) {
    extern __shared__ char dsm[];
    const int tid = threadIdx.x;
    const int warp = tid >> 5, lane = tid & 31;
    const int wm = warp >> 2, wn = warp & 3;
    const int g = lane >> 2, t = lane & 3;
    const int bm = blockIdx.y * 128, bn = blockIdx.x * 128;

    const int l8 = lane & 7;
    const int lm8 = (lane >> 3) & 1;
    const int lk8 = lane >> 4;
    const int arow_off = l8 + (lm8 << 3);

    const uint32_t smb = (uint32_t)__cvta_generic_to_shared(dsm);
    const uint32_t a32b = smb;
    const uint32_t b16b = smb + 3 * CF_A32SZ;
    const uint32_t a16b = b16b + 3 * CF_B16SZ;

    char* const a32g = dsm;
    char* const a16g = dsm + 3 * CF_A32SZ + 3 * CF_B16SZ;

    float acc[4][4][4];
#pragma unroll
    for (int mt = 0; mt < 4; mt++)
#pragma unroll
        for (int nt = 0; nt < 4; nt++)
#pragma unroll
            for (int j = 0; j < 4; j++) acc[mt][nt][j] = 0.0f;

    auto issue = [&](int it) {
        const int k0 = it << 5;
        const uint32_t sa = a32b + (uint32_t)(it % 3) * CF_A32SZ;
        const uint32_t sb = b16b + (uint32_t)(it % 3) * CF_B16SZ;
#pragma unroll
        for (int i = 0; i < 4; i++) {
            int idx = tid + 256 * i;
            int r = idx >> 3, c = (idx & 7) << 2;
            int gr = bm + r;
            int cr = (gr < NN) ? gr : (NN - 1);
            cp_async16p(sa + (uint32_t)(r * 36 + c) * 4u,
                        Ag + (size_t)cr * INDIM + k0 + c, (gr < NN) ? 16 : 0);
        }
#pragma unroll
        for (int i = 0; i < 2; i++) {
            int idx = tid + 256 * i;
            int r = idx >> 4, ch = (idx & 15) << 3;
            cp_async16(sb + (uint32_t)(r * 136 + ch) * 2u,
                       Bg + (size_t)(k0 + r) * HD1 + bn + ch);
        }
        cp_commit();
    };

    issue(0);
    issue(1);

    const int nIter = INDIM >> 5;   // 16
    for (int it = 0; it < nIter; it++) {
        cp_wait<1>();
        __syncthreads();

        {
            char* s32 = a32g + (it % 3) * CF_A32SZ;
            char* d16 = a16g + (it & 1) * CF_A16SZ;
#pragma unroll
            for (int i = 0; i < 4; i++) {
                int idx = tid + 256 * i;
                int r = idx >> 3, c = (idx & 7) << 2;
                float4 v = *(const float4*)(s32 + (r * 36 + c) * 4);
                __half2 h0 = __float22half2_rn(make_float2(v.x, v.y));
                __half2 h1 = __float22half2_rn(make_float2(v.z, v.w));
                uint2 u;
                u.x = *(uint32_t*)&h0;
                u.y = *(uint32_t*)&h1;
                *(uint2*)(d16 + (r * 40 + c) * 2) = u;
            }
        }
        __syncthreads();

        if (it + 2 < nIter) issue(it + 2);

        const uint32_t as_b = a16b + (uint32_t)(it & 1) * CF_A16SZ;
        const uint32_t bs_b = b16b + (uint32_t)(it % 3) * CF_B16SZ;
#pragma unroll
        for (int kk = 0; kk < 2; kk++) {
            uint32_t a[4][4], b[2][4];
            const int acol = (kk << 4) + (lk8 << 3);
#pragma unroll
            for (int mt = 0; mt < 4; mt++) {
                int row = wm * 64 + mt * 16 + arow_off;
                uint32_t addr = as_b + (uint32_t)(row * 40 + acol) * 2u;
                asm volatile(
                    "ldmatrix.sync.aligned.m8n8.x4.shared.b16 {%0,%1,%2,%3}, [%4];"
                    : "=r"(a[mt][0]), "=r"(a[mt][1]), "=r"(a[mt][2]), "=r"(a[mt][3])
                    : "r"(addr));
            }
            const int brow = (kk << 4) + arow_off;
#pragma unroll
            for (int h = 0; h < 2; h++) {
                int ncol = wn * 32 + (h << 4) + (lk8 << 3);
                uint32_t addr = bs_b + (uint32_t)(brow * 136 + ncol) * 2u;
                asm volatile(
                    "ldmatrix.sync.aligned.m8n8.x4.trans.shared.b16 {%0,%1,%2,%3}, [%4];"
                    : "=r"(b[h][0]), "=r"(b[h][1]), "=r"(b[h][2]), "=r"(b[h][3])
                    : "r"(addr));
            }
#pragma unroll
            for (int mt = 0; mt < 4; mt++)
#pragma unroll
                for (int nt = 0; nt < 4; nt++)
                    mma_f16(acc[mt][nt], a[mt],
                            b[nt >> 1][(nt & 1) * 2], b[nt >> 1][(nt & 1) * 2 + 1]);
        }
    }

#pragma unroll
    for (int mt = 0; mt < 4; mt++) {
        int r0 = bm + wm * 64 + mt * 16 + g;
        int r1 = r0 + 8;
#pragma unroll
        for (int nt = 0; nt < 4; nt++) {
            int c = bn + wn * 32 + nt * 8 + t * 2;
            if (r0 < NN)
                *(__half2*)(Cg + (size_t)r0 * HD1 + c) =
                    __float22half2_rn(make_float2(acc[mt][nt][0], acc[mt][nt][1]));
            if (r1 < NN)
                *(__half2*)(Cg + (size_t)r1 * HD1 + c) =
                    __float22half2_rn(make_float2(acc[mt][nt][2], acc[mt][nt][3]));
        }
    }
}

// ---------------- cp.async fp16 GEMM (GEMM2): 128x64 tile, BK=32, 3 stages ----------
template <int BN>
__global__ void __launch_bounds__(256, 2)
k_gemm_cp(const __half* __restrict__ Ag, const __half* __restrict__ Bg,
          __half* __restrict__ Cg, int M, int N, int K,
          int lda, int ldb, int ldc) {
    constexpr int NT = BN / 32;
    constexpr int SA = 40;
    constexpr int SB = BN + 8;
    constexpr int ASZ = 128 * SA * 2;
    constexpr int BSZ = 32 * SB * 2;
    constexpr int STAGES = 3;

    extern __shared__ char dsm[];

    const int tid = threadIdx.x;
    const int warp = tid >> 5, lane = tid & 31;
    const int wm = warp >> 2, wn = warp & 3;
    const int g = lane >> 2, t = lane & 3;
    const int bm = blockIdx.y * 128, bn = blockIdx.x * BN;

    const int l8 = lane & 7;
    const int lm8 = (lane >> 3) & 1;
    const int lk8 = lane >> 4;
    const int arow_off = l8 + (lm8 << 3);

    uint32_t sbase[STAGES];
#pragma unroll
    for (int s = 0; s < STAGES; s++)
        sbase[s] = (uint32_t)__cvta_generic_to_shared(dsm + s * (ASZ + BSZ));

    float acc[4][NT][4];
#pragma unroll
    for (int mt = 0; mt < 4; mt++)
#pragma unroll
        for (int nt = 0; nt < NT; nt++)
#pragma unroll
            for (int j = 0; j < 4; j++) acc[mt][nt][j] = 0.0f;

    const int nIter = K >> 5;

    auto issue = [&](int it) {
        const int k0 = it << 5;
        const uint32_t sa = sbase[it % STAGES];
        const uint32_t sb = sa + ASZ;
#pragma unroll
        for (int i = 0; i < 2; i++) {
            int idx = tid + 256 * i;
            int r = idx >> 2, ch = (idx & 3) << 3;
            int gr = bm + r;
            int cr = (gr < M) ? gr : (M - 1);
            const __half* src = Ag + (size_t)cr * lda + k0 + ch;
            cp_async16p(sa + (uint32_t)(r * SA + ch) * 2u, src, (gr < M) ? 16 : 0);
        }
        {
            int r = tid >> 3, ch = (tid & 7) << 3;
            int gc = bn + ch;
            int cc = (gc < N) ? gc : 0;
            const __half* src = Bg + (size_t)(k0 + r) * ldb + cc;
            cp_async16p(sb + (uint32_t)(r * SB + ch) * 2u, src, (gc < N) ? 16 : 0);
        }
        cp_commit();
    };

    issue(0);
    if (nIter > 1) issue(1); else cp_commit();

    for (int it = 0; it < nIter; it++) {
        cp_wait<1>();
        __syncthreads();
        if (it + 2 < nIter) issue(it + 2);

        const uint32_t as_b = sbase[it % STAGES];
        const uint32_t bs_b = as_b + ASZ;
#pragma unroll
        for (int kk = 0; kk < 2; kk++) {
            uint32_t a[4][4], b[NT / 2][4];
            const int acol = (kk << 4) + (lk8 << 3);
#pragma unroll
            for (int mt = 0; mt < 4; mt++) {
                int rw = wm * 64 + mt * 16 + arow_off;
                uint32_t addr = as_b + (uint32_t)(rw * SA + acol) * 2u;
                asm volatile(
                    "ldmatrix.sync.aligned.m8n8.x4.shared.b16 {%0,%1,%2,%3}, [%4];"
                    : "=r"(a[mt][0]), "=r"(a[mt][1]), "=r"(a[mt][2]), "=r"(a[mt][3])
                    : "r"(addr));
            }
            const int brow = (kk << 4) + arow_off;
#pragma unroll
            for (int h = 0; h < NT / 2; h++) {
                int ncol = wn * (NT * 8) + (h << 4) + (lk8 << 3);
                uint32_t addr = bs_b + (uint32_t)(brow * SB + ncol) * 2u;
                asm volatile(
                    "ldmatrix.sync.aligned.m8n8.x4.trans.shared.b16 {%0,%1,%2,%3}, [%4];"
                    : "=r"(b[h][0]), "=r"(b[h][1]), "=r"(b[h][2]), "=r"(b[h][3])
                    : "r"(addr));
            }
#pragma unroll
            for (int mt = 0; mt < 4; mt++)
#pragma unroll
                for (int nt = 0; nt < NT; nt++)
                    mma_f16(acc[mt][nt], a[mt],
                            b[nt >> 1][(nt & 1) * 2], b[nt >> 1][(nt & 1) * 2 + 1]);
        }
        __syncthreads();
    }

#pragma unroll
    for (int mt = 0; mt < 4; mt++) {
        int r0 = bm + wm * 64 + mt * 16 + g;
        int r1 = r0 + 8;
#pragma unroll
        for (int nt = 0; nt < NT; nt++) {
            int c = bn + wn * (NT * 8) + nt * 8 + t * 2;
            if (c < N) {
                if (r0 < M)
                    *(__half2*)(Cg + (size_t)r0 * ldc + c) =
                        __float22half2_rn(make_float2(acc[mt][nt][0], acc[mt][nt][1]));
                if (r1 < M)
                    *(__half2*)(Cg + (size_t)r1 * ldc + c) =
                        __float22half2_rn(make_float2(acc[mt][nt][2], acc[mt][nt][3]));
            }
        }
    }
}

// ---------------- aggregation layer 1: fp16 gather, 32 lanes/node, unroll 8 ----------
__global__ void __launch_bounds__(256)
k_agg1() {
    int node = blockIdx.x * 8 + (threadIdx.x >> 5);
    int lane = threadIdx.x & 31;
    const __half* H = d_HAh;
    float di = d_dinv[node];
    float sw = di * di;

    const int coff = lane * 8;
    float acc[8];
    {
        uint4 u = *(const uint4*)(H + (size_t)node * HD1 + coff);
#pragma unroll
        for (int j = 0; j < 8; j++) acc[j] = 0.0f;
        acc8(acc, u, sw);
    }

    int e = d_rp[node], e1 = d_rp[node + 1];
    // peel to int4 alignment
    while (e < e1 && (e & 3)) {
        int s0 = d_col[e];
        float w0 = di * d_dinv[s0];
        uint4 u0 = *(const uint4*)(H + (size_t)s0 * HD1 + coff);
        acc8(acc, u0, w0);
        e++;
    }
    // unroll 8: two int4 col loads, 8 row gathers in flight
    for (; e + 7 < e1; e += 8) {
        int4 ca = *(const int4*)&d_col[e];
        int4 cb = *(const int4*)&d_col[e + 4];
        float wa0 = di * d_dinv[ca.x], wa1 = di * d_dinv[ca.y];
        float wa2 = di * d_dinv[ca.z], wa3 = di * d_dinv[ca.w];
        float wb0 = di * d_dinv[cb.x], wb1 = di * d_dinv[cb.y];
        float wb2 = di * d_dinv[cb.z], wb3 = di * d_dinv[cb.w];
        uint4 u0 = *(const uint4*)(H + (size_t)ca.x * HD1 + coff);
        uint4 u1 = *(const uint4*)(H + (size_t)ca.y * HD1 + coff);
        uint4 u2 = *(const uint4*)(H + (size_t)ca.z * HD1 + coff);
        uint4 u3 = *(const uint4*)(H + (size_t)ca.w * HD1 + coff);
        uint4 u4 = *(const uint4*)(H + (size_t)cb.x * HD1 + coff);
        uint4 u5 = *(const uint4*)(H + (size_t)cb.y * HD1 + coff);
        uint4 u6 = *(const uint4*)(H + (size_t)cb.z * HD1 + coff);
        uint4 u7 = *(const uint4*)(H + (size_t)cb.w * HD1 + coff);
        acc8(acc, u0, wa0); acc8(acc, u1, wa1);
        acc8(acc, u2, wa2); acc8(acc, u3, wa3);
        acc8(acc, u4, wb0); acc8(acc, u5, wb1);
        acc8(acc, u6, wb2); acc8(acc, u7, wb3);
    }
    for (; e + 3 < e1; e += 4) {
        int4 cc = *(const int4*)&d_col[e];
        float w0 = di * d_dinv[cc.x];
        float w1 = di * d_dinv[cc.y];
        float w2 = di * d_dinv[cc.z];
        float w3 = di * d_dinv[cc.w];
        uint4 u0 = *(const uint4*)(H + (size_t)cc.x * HD1 + coff);
        uint4 u1 = *(const uint4*)(H + (size_t)cc.y * HD1 + coff);
        uint4 u2 = *(const uint4*)(H + (size_t)cc.z * HD1 + coff);
        uint4 u3 = *(const uint4*)(H + (size_t)cc.w * HD1 + coff);
        acc8(acc, u0, w0); acc8(acc, u1, w1);
        acc8(acc, u2, w2); acc8(acc, u3, w3);
    }
    for (; e < e1; e++) {
        int s0 = d_col[e];
        float w0 = di * d_dinv[s0];
        uint4 u0 = *(const uint4*)(H + (size_t)s0 * HD1 + coff);
        acc8(acc, u0, w0);
    }

    __half* outp = d_HB + (size_t)node * HD1 + coff;
    __half2 p0 = __float22half2_rn(make_float2(softplusf(acc[0]), softplusf(acc[1])));
    __half2 p1 = __float22half2_rn(make_float2(softplusf(acc[2]), softplusf(acc[3])));
    __half2 p2 = __float22half2_rn(make_float2(softplusf(acc[4]), softplusf(acc[5])));
    __half2 p3 = __float22half2_rn(make_float2(softplusf(acc[6]), softplusf(acc[7])));
    uint4 st;
    st.x = *(uint32_t*)&p0;
    st.y = *(uint32_t*)&p1;
    st.z = *(uint32_t*)&p2;
    st.w = *(uint32_t*)&p3;
    *(uint4*)outp = st;
}

// ---------------- aggregation layer 2 + epilogue: 16 lanes/node, unroll 8 -----------
__global__ void __launch_bounds__(256)
k_agg2(float* __restrict__ out) {
    int node = blockIdx.x * 16 + (threadIdx.x >> 4);
    int lane = threadIdx.x & 15;
    const __half* H = d_HAh;
    float di = d_dinv[node];
    float sw = di * di;

    const int coff = lane * 8;
    const __half* srow = H + (size_t)node * HD2P;
    float acc[8];
    {
        uint4 u = *(const uint4*)(srow + coff);
#pragma unroll
        for (int j = 0; j < 8; j++) acc[j] = 0.0f;
        acc8(acc, u, sw);
    }
    float acck = (lane == 0) ? __half2float(srow[128]) * sw : 0.0f;

    int e = d_rp[node], e1 = d_rp[node + 1];
    for (; e + 7 < e1; e += 8) {
        int sc[8];
#pragma unroll
        for (int q = 0; q < 8; q++) sc[q] = d_col[e + q];
        float w[8];
#pragma unroll
        for (int q = 0; q < 8; q++) w[q] = di * d_dinv[sc[q]];
        uint4 u[8];
#pragma unroll
        for (int q = 0; q < 8; q++)
            u[q] = *(const uint4*)(H + (size_t)sc[q] * HD2P + coff);
#pragma unroll
        for (int q = 0; q < 8; q++) acc8(acc, u[q], w[q]);
        if (lane == 0) {
#pragma unroll
            for (int q = 0; q < 8; q++)
                acck += __half2float(H[(size_t)sc[q] * HD2P + 128]) * w[q];
        }
    }
    for (; e < e1; e++) {
        int s0 = d_col[e];
        float w0 = di * d_dinv[s0];
        uint4 u0 = *(const uint4*)(H + (size_t)s0 * HD2P + coff);
        acc8(acc, u0, w0);
        if (lane == 0) acck += __half2float(H[(size_t)s0 * HD2P + 128]) * w0;
    }

    float lbd[8];
#pragma unroll
    for (int j = 0; j < 8; j++) lbd[j] = softplusf(acc[j]);

    float g = 0.0f, kap = 0.0f;
    if (lane == 0) {
        kap = softplusf(acck) + 0.1f;
        g = expf(lgammaf(1.0f + 1.0f / kap));
    }
    g = __shfl_sync(0xffffffffu, g, (threadIdx.x & 16), 32);

    const size_t ZOFF = 0;
    const size_t LOFF = (size_t)NN * 128;
    const size_t KOFF = (size_t)NN * 256;

    float* zp = out + ZOFF + (size_t)node * 128 + coff;
    float* lp = out + LOFF + (size_t)node * 128 + coff;
    *(float4*)zp       = make_float4(lbd[0] * g, lbd[1] * g, lbd[2] * g, lbd[3] * g);
    *(float4*)(zp + 4) = make_float4(lbd[4] * g, lbd[5] * g, lbd[6] * g, lbd[7] * g);
    *(float4*)lp       = make_float4(lbd[0], lbd[1], lbd[2], lbd[3]);
    *(float4*)(lp + 4) = make_float4(lbd[4], lbd[5], lbd[6], lbd[7]);
    if (lane == 0) out[KOFF + node] = kap;
}

// ---------------- launch ----------------
extern "C" void kernel_launch(void* const* d_in, const int* in_sizes, int n_in,
                              void* d_out, int out_size) {
    const float* x  = (const float*)d_in[0];
    const int* eidx = (const int*)d_in[1];
    const float* W0 = (const float*)d_in[2];
    const float* W1 = (const float*)d_in[3];
    float* out = (float*)d_out;

    const int4* src4 = (const int4*)eidx;
    const int4* dst4 = (const int4*)(eidx + NE);

    __half* W0h; cudaGetSymbolAddress((void**)&W0h, d_W0h);
    __half* W1h; cudaGetSymbolAddress((void**)&W1h, d_W1h);
    __half* HAh; cudaGetSymbolAddress((void**)&HAh, d_HAh);
    __half* HB;  cudaGetSymbolAddress((void**)&HB, d_HB);

    const int smem64 = 3 * (10240 + 32 * (64 + 8) * 2);
    cudaFuncSetAttribute(k_gemm_cp<64>, cudaFuncAttributeMaxDynamicSharedMemorySize, smem64);
    cudaFuncSetAttribute(k_gemm_cf, cudaFuncAttributeMaxDynamicSharedMemorySize, CF_SMEM);

    // Side stream + events (capture-legal fork/join, proven R6-R15).
    cudaStream_t s1;
    cudaStreamCreateWithFlags(&s1, cudaStreamNonBlocking);
    cudaEvent_t ef, ej;
    cudaEventCreateWithFlags(&ef, cudaEventDisableTiming);
    cudaEventCreateWithFlags(&ej, cudaEventDisableTiming);

    cudaEventRecord(ef, 0);
    cudaStreamWaitEvent(s1, ef, 0);

    // main: W0/W1 -> fp16 (submission 0)
    k_initW<<<(INITW_N + 255) / 256, 256>>>(W0, W1);

    // side: CSR part 1 — d_cnt zero by invariant (submissions 1,2)
    k_hist<<<(NE / 4 + 255) / 256, 256, 0, s1>>>(dst4);
    k_blocksum<<<NBLK, SCAN_B, 0, s1>>>();

    // main: GEMM1 fused-convert (submission 3 — ncu capture slot)
    {
        dim3 grid(2, (NN + 127) / 128);
        k_gemm_cf<<<grid, 256, CF_SMEM>>>(x, W0h, HAh);
    }

    // side: CSR part 2 (overlaps GEMM1); k_local re-zeroes d_cnt
    k_bscan<<<1, 128, 0, s1>>>();
    k_local<<<NBLK, SCAN_B, 0, s1>>>();
    k_fill<<<(NE / 4 + 255) / 256, 256, 0, s1>>>(src4, dst4);
    cudaEventRecord(ej, s1);

    // join: agg1 needs GEMM1 + CSR
    cudaStreamWaitEvent(0, ej, 0);

    // AGG1 + softplus -> HB (fp16)
    k_agg1<<<NN / 8, 256>>>();
    // GEMM2: HAh(stride 136) = HB @ W1h  (50000x136, K=256), BN=64 x 3
    {
        dim3 grid(3, (NN + 127) / 128);
        k_gemm_cp<64><<<grid, 256, smem64>>>(HB, W1h, HAh, NN, HD2P, HD1,
                                             HD1, HD2P, HD2P);
    }
    // AGG2 + softplus + Weibull epilogue -> out
    k_agg2<<<NN / 16, 256>>>(out);
}

// round 17
// speedup vs baseline: 1.0362x; 1.0278x over previous
#include <cuda_runtime.h>
#include <cuda_fp16.h>
#include <math.h>
#include <stdint.h>

// Problem constants
#define NN    50000
#define NE    1600000
#define INDIM 512
#define HD1   256
#define HD2R  129     // real cols of layer 2
#define HD2P  136     // padded stride in halves (272B, 16B-aligned)

#define SCAN_B 512
#define NBLK   ((NN + SCAN_B - 1) / SCAN_B)   // 98

#define XCHUNKS (NN * INDIM / 8)        // 3,200,000 8-elem chunks
#define W0CHUNKS (INDIM * HD1 / 8)      // 16,384

// ---------------- static scratch (no allocations allowed) ----------------
// d_cnt invariant: zero at module load; k_local re-zeroes it after consuming,
// so every kernel_launch call (and every graph replay) sees d_cnt == 0.
__device__ __half d_Xh[(size_t)NN * INDIM];   // fp16 copy of x
__device__ __half d_W0h[INDIM * HD1];         // fp16 W0
__device__ __half d_W1h[HD1 * HD2P];          // fp16 W1, padded
__device__ __half d_HAh[(size_t)NN * HD1];    // fp16 XW0; reused as H1W1 (stride HD2P)
__device__ __half d_HB[(size_t)NN * HD1];     // fp16 softplus(agg1)
__device__ int    d_col[NE];
__device__ int    d_rp[NN + 1];
__device__ int    d_cur[NN];
__device__ int    d_cnt[NN];
__device__ float  d_dinv[NN];
__device__ int    d_bsum[NBLK];
__device__ int    d_boff[NBLK];

// ---------------- helpers ----------------
__device__ __forceinline__ float softplusf(float x) {
    return fmaxf(x, 0.0f) + log1pf(expf(-fabsf(x)));
}

__device__ __forceinline__ void mma_f16(float c[4], const uint32_t a[4],
                                        uint32_t b0, uint32_t b1) {
    asm volatile(
        "mma.sync.aligned.m16n8k16.row.col.f32.f16.f16.f32 "
        "{%0,%1,%2,%3}, {%4,%5,%6,%7}, {%8,%9}, {%0,%1,%2,%3};\n"
        : "+f"(c[0]), "+f"(c[1]), "+f"(c[2]), "+f"(c[3])
        : "r"(a[0]), "r"(a[1]), "r"(a[2]), "r"(a[3]), "r"(b0), "r"(b1));
}

__device__ __forceinline__ void cp_async16p(uint32_t smem_dst, const void* gsrc, int src_bytes) {
    asm volatile("cp.async.cg.shared.global [%0], [%1], 16, %2;\n"
                 :: "r"(smem_dst), "l"(gsrc), "r"(src_bytes) : "memory");
}
__device__ __forceinline__ void cp_commit() {
    asm volatile("cp.async.commit_group;\n" ::: "memory");
}
template <int N>
__device__ __forceinline__ void cp_wait() {
    asm volatile("cp.async.wait_group %0;\n" :: "n"(N) : "memory");
}

__device__ __forceinline__ uint4 pack8(float4 f0, float4 f1) {
    __half2 h0 = __float22half2_rn(make_float2(f0.x, f0.y));
    __half2 h1 = __float22half2_rn(make_float2(f0.z, f0.w));
    __half2 h2 = __float22half2_rn(make_float2(f1.x, f1.y));
    __half2 h3 = __float22half2_rn(make_float2(f1.z, f1.w));
    uint4 u;
    u.x = *(uint32_t*)&h0; u.y = *(uint32_t*)&h1;
    u.z = *(uint32_t*)&h2; u.w = *(uint32_t*)&h3;
    return u;
}

// ---------------- fp32 -> fp16 conversion (x and W0) ----------------
__global__ void k_cvtx(const float* __restrict__ x, const float* __restrict__ W0) {
    int i = blockIdx.x * blockDim.x + threadIdx.x;
    if (i < XCHUNKS) {
        const float4* p = (const float4*)x + (size_t)i * 2;
        ((uint4*)d_Xh)[i] = pack8(p[0], p[1]);
    }
    if (i < W0CHUNKS) {
        const float4* p = (const float4*)W0 + (size_t)i * 2;
        ((uint4*)d_W0h)[i] = pack8(p[0], p[1]);
    }
}

// ---------------- init: pad/convert W1 only (d_cnt zero by invariant) ----------------
__global__ void k_init(const float* __restrict__ W1) {
    int i = blockIdx.x * blockDim.x + threadIdx.x;
    if (i < HD1 * HD2P) {
        int k = i / HD2P, n = i % HD2P;
        d_W1h[i] = __float2half((n < HD2R) ? W1[k * HD2R + n] : 0.0f);
    }
}

__global__ void k_hist(const int4* __restrict__ dst4) {
    int e = blockIdx.x * blockDim.x + threadIdx.x;
    if (e < NE / 4) {
        int4 d = dst4[e];
        atomicAdd(&d_cnt[d.x], 1);
        atomicAdd(&d_cnt[d.y], 1);
        atomicAdd(&d_cnt[d.z], 1);
        atomicAdd(&d_cnt[d.w], 1);
    }
}

__global__ void k_blocksum() {
    __shared__ int sh[SCAN_B];
    int t = threadIdx.x;
    int i = blockIdx.x * SCAN_B + t;
    sh[t] = (i < NN) ? d_cnt[i] : 0;
    __syncthreads();
    for (int off = SCAN_B / 2; off > 0; off >>= 1) {
        if (t < off) sh[t] += sh[t + off];
        __syncthreads();
    }
    if (t == 0) d_bsum[blockIdx.x] = sh[0];
}

__global__ void k_bscan() {
    __shared__ int sh[128];
    int t = threadIdx.x;
    int v = (t < NBLK) ? d_bsum[t] : 0;
    sh[t] = v;
    __syncthreads();
    for (int off = 1; off < 128; off <<= 1) {
        int add = (t >= off) ? sh[t - off] : 0;
        __syncthreads();
        sh[t] += add;
        __syncthreads();
    }
    if (t < NBLK) d_boff[t] = sh[t] - v;
}

__global__ void k_local() {
    __shared__ int sh[SCAN_B];
    int t = threadIdx.x;
    int i = blockIdx.x * SCAN_B + t;
    int v = (i < NN) ? d_cnt[i] : 0;
    sh[t] = v;
    __syncthreads();
    for (int off = 1; off < SCAN_B; off <<= 1) {
        int add = (t >= off) ? sh[t - off] : 0;
        __syncthreads();
        sh[t] += add;
        __syncthreads();
    }
    if (i < NN) {
        int incl = sh[t];
        int base = d_boff[blockIdx.x] + incl - v;
        d_rp[i] = base;
        d_cur[i] = base;
        d_dinv[i] = rsqrtf((float)v + 1.0f);
        d_cnt[i] = 0;   // restore zero invariant for next launch/replay
        if (i == NN - 1) d_rp[NN] = d_boff[blockIdx.x] + incl;
    }
}

__global__ void k_fill(const int4* __restrict__ src4, const int4* __restrict__ dst4) {
    int e = blockIdx.x * blockDim.x + threadIdx.x;
    if (e >= NE / 4) return;
    int4 s = src4[e];
    int4 d = dst4[e];
    d_col[atomicAdd(&d_cur[d.x], 1)] = s.x;
    d_col[atomicAdd(&d_cur[d.y], 1)] = s.y;
    d_col[atomicAdd(&d_cur[d.z], 1)] = s.z;
    d_col[atomicAdd(&d_cur[d.w], 1)] = s.w;
}

// ---------------- cp.async fp16 GEMM: 128xBN tile, BK=32, 3 stages, 256 thr ----------
template <int BN>
__global__ void __launch_bounds__(256, 2)
k_gemm_cp(const __half* __restrict__ Ag, const __half* __restrict__ Bg,
          __half* __restrict__ Cg, int M, int N, int K,
          int lda, int ldb, int ldc) {
    constexpr int NT = BN / 32;
    constexpr int SA = 40;
    constexpr int SB = BN + 8;
    constexpr int ASZ = 128 * SA * 2;
    constexpr int BSZ = 32 * SB * 2;
    constexpr int STAGES = 3;

    extern __shared__ char dsm[];

    const int tid = threadIdx.x;
    const int warp = tid >> 5, lane = tid & 31;
    const int wm = warp >> 2, wn = warp & 3;
    const int g = lane >> 2, t = lane & 3;
    const int bm = blockIdx.y * 128, bn = blockIdx.x * BN;

    const int l8 = lane & 7;
    const int lm8 = (lane >> 3) & 1;
    const int lk8 = lane >> 4;
    const int arow_off = l8 + (lm8 << 3);

    uint32_t sbase[STAGES];
#pragma unroll
    for (int s = 0; s < STAGES; s++)
        sbase[s] = (uint32_t)__cvta_generic_to_shared(dsm + s * (ASZ + BSZ));

    float acc[4][NT][4];
#pragma unroll
    for (int mt = 0; mt < 4; mt++)
#pragma unroll
        for (int nt = 0; nt < NT; nt++)
#pragma unroll
            for (int j = 0; j < 4; j++) acc[mt][nt][j] = 0.0f;

    const int nIter = K >> 5;

    auto issue = [&](int it) {
        const int k0 = it << 5;
        const uint32_t sa = sbase[it % STAGES];
        const uint32_t sb = sa + ASZ;
#pragma unroll
        for (int i = 0; i < 2; i++) {
            int idx = tid + 256 * i;
            int r = idx >> 2, ch = (idx & 3) << 3;
            int gr = bm + r;
            int cr = (gr < M) ? gr : (M - 1);
            const __half* src = Ag + (size_t)cr * lda + k0 + ch;
            cp_async16p(sa + (uint32_t)(r * SA + ch) * 2u, src, (gr < M) ? 16 : 0);
        }
        if (BN == 128) {
#pragma unroll
            for (int i = 0; i < 2; i++) {
                int idx = tid + 256 * i;
                int r = idx >> 4, ch = (idx & 15) << 3;
                int gc = bn + ch;
                int cc = (gc < N) ? gc : 0;
                const __half* src = Bg + (size_t)(k0 + r) * ldb + cc;
                cp_async16p(sb + (uint32_t)(r * SB + ch) * 2u, src, (gc < N) ? 16 : 0);
            }
        } else {  // BN == 64
            int r = tid >> 3, ch = (tid & 7) << 3;
            int gc = bn + ch;
            int cc = (gc < N) ? gc : 0;
            const __half* src = Bg + (size_t)(k0 + r) * ldb + cc;
            cp_async16p(sb + (uint32_t)(r * SB + ch) * 2u, src, (gc < N) ? 16 : 0);
        }
        cp_commit();
    };

    issue(0);
    if (nIter > 1) issue(1); else cp_commit();

    for (int it = 0; it < nIter; it++) {
        cp_wait<1>();
        __syncthreads();
        if (it + 2 < nIter) issue(it + 2);

        const uint32_t as_b = sbase[it % STAGES];
        const uint32_t bs_b = as_b + ASZ;
#pragma unroll
        for (int kk = 0; kk < 2; kk++) {
            uint32_t a[4][4], b[NT / 2][4];
            const int acol = (kk << 4) + (lk8 << 3);
#pragma unroll
            for (int mt = 0; mt < 4; mt++) {
                int rw = wm * 64 + mt * 16 + arow_off;
                uint32_t addr = as_b + (uint32_t)(rw * SA + acol) * 2u;
                asm volatile(
                    "ldmatrix.sync.aligned.m8n8.x4.shared.b16 {%0,%1,%2,%3}, [%4];"
                    : "=r"(a[mt][0]), "=r"(a[mt][1]), "=r"(a[mt][2]), "=r"(a[mt][3])
                    : "r"(addr));
            }
            const int brow = (kk << 4) + arow_off;
#pragma unroll
            for (int h = 0; h < NT / 2; h++) {
                int ncol = wn * (NT * 8) + (h << 4) + (lk8 << 3);
                uint32_t addr = bs_b + (uint32_t)(brow * SB + ncol) * 2u;
                asm volatile(
                    "ldmatrix.sync.aligned.m8n8.x4.trans.shared.b16 {%0,%1,%2,%3}, [%4];"
                    : "=r"(b[h][0]), "=r"(b[h][1]), "=r"(b[h][2]), "=r"(b[h][3])
                    : "r"(addr));
            }
#pragma unroll
            for (int mt = 0; mt < 4; mt++)
#pragma unroll
                for (int nt = 0; nt < NT; nt++)
                    mma_f16(acc[mt][nt], a[mt],
                            b[nt >> 1][(nt & 1) * 2], b[nt >> 1][(nt & 1) * 2 + 1]);
        }
        __syncthreads();
    }

#pragma unroll
    for (int mt = 0; mt < 4; mt++) {
        int r0 = bm + wm * 64 + mt * 16 + g;
        int r1 = r0 + 8;
#pragma unroll
        for (int nt = 0; nt < NT; nt++) {
            int c = bn + wn * (NT * 8) + nt * 8 + t * 2;
            if (c < N) {
                if (r0 < M)
                    *(__half2*)(Cg + (size_t)r0 * ldc + c) =
                        __float22half2_rn(make_float2(acc[mt][nt][0], acc[mt][nt][1]));
                if (r1 < M)
                    *(__half2*)(Cg + (size_t)r1 * ldc + c) =
                        __float22half2_rn(make_float2(acc[mt][nt][2], acc[mt][nt][3]));
            }
        }
    }
}

// ---------------- aggregation layer 1: fp16 gather, 32 lanes/node -> fp16 out ----------------
__global__ void __launch_bounds__(256)
k_agg1() {
    int node = blockIdx.x * 8 + (threadIdx.x >> 5);
    int lane = threadIdx.x & 31;
    const __half* H = d_HAh;
    float di = d_dinv[node];
    float sw = di * di;

    const int coff = lane * 8;
    float acc[8];
    {
        uint4 u = *(const uint4*)(H + (size_t)node * HD1 + coff);
        const __half2* h2 = (const __half2*)&u;
#pragma unroll
        for (int j = 0; j < 4; j++) {
            float2 f = __half22float2(h2[j]);
            acc[2 * j] = f.x * sw;
            acc[2 * j + 1] = f.y * sw;
        }
    }

    int e = d_rp[node], e1 = d_rp[node + 1];
    while (e < e1 && (e & 3)) {
        int s0 = d_col[e];
        float w0 = di * d_dinv[s0];
        uint4 u0 = *(const uint4*)(H + (size_t)s0 * HD1 + coff);
        const __half2* a0 = (const __half2*)&u0;
#pragma unroll
        for (int j = 0; j < 4; j++) {
            float2 f0 = __half22float2(a0[j]);
            acc[2 * j]     += f0.x * w0;
            acc[2 * j + 1] += f0.y * w0;
        }
        e++;
    }
    for (; e + 3 < e1; e += 4) {
        int4 cc = *(const int4*)&d_col[e];
        float w0 = di * d_dinv[cc.x];
        float w1 = di * d_dinv[cc.y];
        float w2 = di * d_dinv[cc.z];
        float w3 = di * d_dinv[cc.w];
        uint4 u0 = *(const uint4*)(H + (size_t)cc.x * HD1 + coff);
        uint4 u1 = *(const uint4*)(H + (size_t)cc.y * HD1 + coff);
        uint4 u2 = *(const uint4*)(H + (size_t)cc.z * HD1 + coff);
        uint4 u3 = *(const uint4*)(H + (size_t)cc.w * HD1 + coff);
        const __half2* a0 = (const __half2*)&u0;
        const __half2* a1 = (const __half2*)&u1;
        const __half2* a2 = (const __half2*)&u2;
        const __half2* a3 = (const __half2*)&u3;
#pragma unroll
        for (int j = 0; j < 4; j++) {
            float2 f0 = __half22float2(a0[j]);
            float2 f1 = __half22float2(a1[j]);
            float2 f2 = __half22float2(a2[j]);
            float2 f3 = __half22float2(a3[j]);
            acc[2 * j]     += f0.x * w0 + f1.x * w1 + f2.x * w2 + f3.x * w3;
            acc[2 * j + 1] += f0.y * w0 + f1.y * w1 + f2.y * w2 + f3.y * w3;
        }
    }
    for (; e < e1; e++) {
        int s0 = d_col[e];
        float w0 = di * d_dinv[s0];
        uint4 u0 = *(const uint4*)(H + (size_t)s0 * HD1 + coff);
        const __half2* a0 = (const __half2*)&u0;
#pragma unroll
        for (int j = 0; j < 4; j++) {
            float2 f0 = __half22float2(a0[j]);
            acc[2 * j]     += f0.x * w0;
            acc[2 * j + 1] += f0.y * w0;
        }
    }

    __half* outp = d_HB + (size_t)node * HD1 + coff;
    __half2 p0 = __float22half2_rn(make_float2(softplusf(acc[0]), softplusf(acc[1])));
    __half2 p1 = __float22half2_rn(make_float2(softplusf(acc[2]), softplusf(acc[3])));
    __half2 p2 = __float22half2_rn(make_float2(softplusf(acc[4]), softplusf(acc[5])));
    __half2 p3 = __float22half2_rn(make_float2(softplusf(acc[6]), softplusf(acc[7])));
    uint4 st;
    st.x = *(uint32_t*)&p0;
    st.y = *(uint32_t*)&p1;
    st.z = *(uint32_t*)&p2;
    st.w = *(uint32_t*)&p3;
    *(uint4*)outp = st;
}

// ---------------- aggregation layer 2 + epilogue: fp16 gather, 16 lanes/node ----------------
__global__ void __launch_bounds__(256)
k_agg2(float* __restrict__ out) {
    int node = blockIdx.x * 16 + (threadIdx.x >> 4);
    int lane = threadIdx.x & 15;
    const __half* H = d_HAh;
    float di = d_dinv[node];
    float sw = di * di;

    const int coff = lane * 8;
    const __half* srow = H + (size_t)node * HD2P;
    float acc[8];
    {
        uint4 u = *(const uint4*)(srow + coff);
        const __half2* h2 = (const __half2*)&u;
#pragma unroll
        for (int j = 0; j < 4; j++) {
            float2 f = __half22float2(h2[j]);
            acc[2 * j] = f.x * sw;
            acc[2 * j + 1] = f.y * sw;
        }
    }
    float acck = (lane == 0) ? __half2float(srow[128]) * sw : 0.0f;

    int e = d_rp[node], e1 = d_rp[node + 1];
    for (; e + 3 < e1; e += 4) {
        int s0 = d_col[e], s1 = d_col[e + 1], s2 = d_col[e + 2], s3 = d_col[e + 3];
        float w0 = di * d_dinv[s0];
        float w1 = di * d_dinv[s1];
        float w2 = di * d_dinv[s2];
        float w3 = di * d_dinv[s3];
        const __half* r0 = H + (size_t)s0 * HD2P;
        const __half* r1 = H + (size_t)s1 * HD2P;
        const __half* r2 = H + (size_t)s2 * HD2P;
        const __half* r3 = H + (size_t)s3 * HD2P;
        uint4 u0 = *(const uint4*)(r0 + coff);
        uint4 u1 = *(const uint4*)(r1 + coff);
        uint4 u2 = *(const uint4*)(r2 + coff);
        uint4 u3 = *(const uint4*)(r3 + coff);
        const __half2* a0 = (const __half2*)&u0;
        const __half2* a1 = (const __half2*)&u1;
        const __half2* a2 = (const __half2*)&u2;
        const __half2* a3 = (const __half2*)&u3;
#pragma unroll
        for (int j = 0; j < 4; j++) {
            float2 f0 = __half22float2(a0[j]);
            float2 f1 = __half22float2(a1[j]);
            float2 f2 = __half22float2(a2[j]);
            float2 f3 = __half22float2(a3[j]);
            acc[2 * j]     += f0.x * w0 + f1.x * w1 + f2.x * w2 + f3.x * w3;
            acc[2 * j + 1] += f0.y * w0 + f1.y * w1 + f2.y * w2 + f3.y * w3;
        }
        if (lane == 0)
            acck += __half2float(r0[128]) * w0 + __half2float(r1[128]) * w1
                  + __half2float(r2[128]) * w2 + __half2float(r3[128]) * w3;
    }
    for (; e < e1; e++) {
        int s0 = d_col[e];
        float w0 = di * d_dinv[s0];
        const __half* r0 = H + (size_t)s0 * HD2P;
        uint4 u0 = *(const uint4*)(r0 + coff);
        const __half2* a0 = (const __half2*)&u0;
#pragma unroll
        for (int j = 0; j < 4; j++) {
            float2 f0 = __half22float2(a0[j]);
            acc[2 * j]     += f0.x * w0;
            acc[2 * j + 1] += f0.y * w0;
        }
        if (lane == 0) acck += __half2float(r0[128]) * w0;
    }

    float lbd[8];
#pragma unroll
    for (int j = 0; j < 8; j++) lbd[j] = softplusf(acc[j]);

    float g = 0.0f, kap = 0.0f;
    if (lane == 0) {
        kap = softplusf(acck) + 0.1f;
        g = expf(lgammaf(1.0f + 1.0f / kap));
    }
    g = __shfl_sync(0xffffffffu, g, (threadIdx.x & 16), 32);

    const size_t ZOFF = 0;
    const size_t LOFF = (size_t)NN * 128;
    const size_t KOFF = (size_t)NN * 256;

    float* zp = out + ZOFF + (size_t)node * 128 + coff;
    float* lp = out + LOFF + (size_t)node * 128 + coff;
    *(float4*)zp       = make_float4(lbd[0] * g, lbd[1] * g, lbd[2] * g, lbd[3] * g);
    *(float4*)(zp + 4) = make_float4(lbd[4] * g, lbd[5] * g, lbd[6] * g, lbd[7] * g);
    *(float4*)lp       = make_float4(lbd[0], lbd[1], lbd[2], lbd[3]);
    *(float4*)(lp + 4) = make_float4(lbd[4], lbd[5], lbd[6], lbd[7]);
    if (lane == 0) out[KOFF + node] = kap;
}

// ---------------- launch ----------------
extern "C" void kernel_launch(void* const* d_in, const int* in_sizes, int n_in,
                              void* d_out, int out_size) {
    const float* x  = (const float*)d_in[0];
    const int* eidx = (const int*)d_in[1];
    const float* W0 = (const float*)d_in[2];
    const float* W1 = (const float*)d_in[3];
    float* out = (float*)d_out;

    const int4* src4 = (const int4*)eidx;
    const int4* dst4 = (const int4*)(eidx + NE);

    __half* Xh;  cudaGetSymbolAddress((void**)&Xh, d_Xh);
    __half* W0h; cudaGetSymbolAddress((void**)&W0h, d_W0h);
    __half* W1h; cudaGetSymbolAddress((void**)&W1h, d_W1h);
    __half* HAh; cudaGetSymbolAddress((void**)&HAh, d_HAh);
    __half* HB;  cudaGetSymbolAddress((void**)&HB, d_HB);

    // dynamic smem sizes: 3 stages * (A 10240B + B bytes)
    const int smem128 = 3 * (10240 + 32 * (128 + 8) * 2);  // 56832
    const int smem64  = 3 * (10240 + 32 * (64 + 8) * 2);   // 44544
    cudaFuncSetAttribute(k_gemm_cp<128>, cudaFuncAttributeMaxDynamicSharedMemorySize, smem128);
    cudaFuncSetAttribute(k_gemm_cp<64>,  cudaFuncAttributeMaxDynamicSharedMemorySize, smem64);

    // Side stream + events (capture-legal fork/join, proven R6-R16).
    cudaStream_t s1;
    cudaStreamCreateWithFlags(&s1, cudaStreamNonBlocking);
    cudaEvent_t ef, ej;
    cudaEventCreateWithFlags(&ef, cudaEventDisableTiming);
    cudaEventCreateWithFlags(&ej, cudaEventDisableTiming);

    cudaEventRecord(ef, 0);
    cudaStreamWaitEvent(s1, ef, 0);

    // main: x/W0 -> fp16 (submission 0)
    k_cvtx<<<(XCHUNKS + 255) / 256, 256>>>(x, W0);

    // side: W1 convert + hist (submissions 1,2) — d_cnt zero by invariant
    k_init<<<(HD1 * HD2P + 255) / 256, 256, 0, s1>>>(W1);
    k_hist<<<(NE / 4 + 255) / 256, 256, 0, s1>>>(dst4);

    // main: GEMM1 (submission 3 — ncu capture slot):
    // HAh = Xh @ W0h  (50000x256, K=512), BN=128
    {
        dim3 grid(2, (NN + 127) / 128);
        k_gemm_cp<128><<<grid, 256, smem128>>>(Xh, W0h, HAh, NN, HD1, INDIM,
                                               INDIM, HD1, HD1);
    }

    // side: CSR part 2 (overlaps cvtx+GEMM1); k_local re-zeroes d_cnt
    k_blocksum<<<NBLK, SCAN_B, 0, s1>>>();
    k_bscan<<<1, 128, 0, s1>>>();
    k_local<<<NBLK, SCAN_B, 0, s1>>>();
    k_fill<<<(NE / 4 + 255) / 256, 256, 0, s1>>>(src4, dst4);
    cudaEventRecord(ej, s1);

    // join: agg1 needs GEMM1 + CSR; GEMM2 needs W1h (also from side)
    cudaStreamWaitEvent(0, ej, 0);

    // AGG1 + softplus -> HB (fp16)
    k_agg1<<<NN / 8, 256>>>();
    // GEMM2: HAh(stride 136) = HB @ W1h  (50000x136, K=256), BN=64
    {
        dim3 grid(3, (NN + 127) / 128);
        k_gemm_cp<64><<<grid, 256, smem64>>>(HB, W1h, HAh, NN, HD2P, HD1,
                                             HD1, HD2P, HD2P);
    }
    // AGG2 + softplus + Weibull epilogue -> out
    k_agg2<<<NN / 16, 256>>>(out);
}